// round 9
// baseline (speedup 1.0000x reference)
#include <cuda_runtime.h>
#include <cuda_fp16.h>
#include <cstdint>
#include <cstddef>

// ============================================================================
// GAT fusion, B=8192, N=12, D=256, SEL={0,3,6,9}.  sm_100 legacy-mma edition.
// R8 evidence: GEMM is smem-crossbar bound (tensor 52% == tensor/LDS cycle
// ratio 384/768). Fix: CTA tile 128x256, warp tile 64x64 -> LDS/mma halved,
// tensor becomes binding pipe. K,Q fp16x3; V,out fp16x1 (rel_err ~3.8e-4).
// ============================================================================

#define BATCH   8192
#define NNODE   12
#define DIM     256
#define M_VK    (BATCH * NNODE)     // 98304
#define M_SEL   (BATCH * 4)         // 32768

// ---------------- scratch (device globals; no allocation) -------------------
__device__ __half g_hh[M_VK * DIM], g_hl[M_VK * DIM];    // h split (fp16)
__device__ float g_Wh1[M_VK * DIM];
__device__ float g_k1 [M_VK * DIM];
__device__ float g_q1 [M_SEL * DIM];
__device__ __half g_f1h[M_SEL * DIM];
__device__ float g_bc [DIM];
__device__ float g_Wc_part[8 * DIM * DIM];
__device__ __half g_Wv_h[DIM*DIM], g_Wv_l[DIM*DIM];
__device__ __half g_Wk_h[DIM*DIM], g_Wk_l[DIM*DIM];
__device__ __half g_Wq_h[DIM*DIM], g_Wq_l[DIM*DIM];
__device__ __half g_Wc_h[DIM*DIM];

// ---------------- helpers ----------------------------------------------------
__device__ __forceinline__ uint32_t smem_u32(const void* p) {
    return (uint32_t)__cvta_generic_to_shared(p);
}
__device__ __forceinline__ void ldmatrix_x4(uint32_t& r0, uint32_t& r1,
                                            uint32_t& r2, uint32_t& r3, uint32_t addr) {
    asm volatile("ldmatrix.sync.aligned.m8n8.x4.shared.b16 {%0,%1,%2,%3}, [%4];\n"
                 : "=r"(r0), "=r"(r1), "=r"(r2), "=r"(r3) : "r"(addr));
}
__device__ __forceinline__ void ldmatrix_x2(uint32_t& r0, uint32_t& r1, uint32_t addr) {
    asm volatile("ldmatrix.sync.aligned.m8n8.x2.shared.b16 {%0,%1}, [%2];\n"
                 : "=r"(r0), "=r"(r1) : "r"(addr));
}
__device__ __forceinline__ void mma_f16(float c[4],
                                        uint32_t a0, uint32_t a1, uint32_t a2, uint32_t a3,
                                        uint32_t b0, uint32_t b1) {
    asm volatile("mma.sync.aligned.m16n8k16.row.col.f32.f16.f16.f32 "
                 "{%0,%1,%2,%3}, {%4,%5,%6,%7}, {%8,%9}, {%0,%1,%2,%3};\n"
                 : "+f"(c[0]), "+f"(c[1]), "+f"(c[2]), "+f"(c[3])
                 : "r"(a0), "r"(a1), "r"(a2), "r"(a3), "r"(b0), "r"(b1));
}
__device__ __forceinline__ void cp16(uint32_t dst, const void* src) {
    asm volatile("cp.async.cg.shared.global [%0], [%1], 16;\n" :: "r"(dst), "l"(src));
}

// ---------------- prologue kernels -------------------------------------------
__global__ void convert_w_kernel(const float* __restrict__ src,
                                 __half* __restrict__ hi,
                                 __half* __restrict__ lo) {
    int i = blockIdx.x * 256 + threadIdx.x;
    float x = src[i];
    __half h = __float2half_rn(x);
    hi[i] = h;
    lo[i] = __float2half_rn(x - __half2float(h));
}

__global__ void convert_h_kernel(const float* __restrict__ src,
                                 __half* __restrict__ hi,
                                 __half* __restrict__ lo) {
    size_t i = ((size_t)blockIdx.x * 256 + threadIdx.x) * 8;
    float4 a = *(const float4*)(src + i);
    float4 b = *(const float4*)(src + i + 4);
    float x[8] = {a.x, a.y, a.z, a.w, b.x, b.y, b.z, b.w};
    uint32_t hw[4], lw[4];
    #pragma unroll
    for (int g = 0; g < 4; ++g) {
        __half h0 = __float2half_rn(x[2*g]);
        __half h1 = __float2half_rn(x[2*g+1]);
        __half l0 = __float2half_rn(x[2*g]   - __half2float(h0));
        __half l1 = __float2half_rn(x[2*g+1] - __half2float(h1));
        hw[g] = (uint32_t)__half_as_ushort(h0) | ((uint32_t)__half_as_ushort(h1) << 16);
        lw[g] = (uint32_t)__half_as_ushort(l0) | ((uint32_t)__half_as_ushort(l1) << 16);
    }
    *(uint4*)(hi + i) = make_uint4(hw[0], hw[1], hw[2], hw[3]);
    *(uint4*)(lo + i) = make_uint4(lw[0], lw[1], lw[2], lw[3]);
}

// ---- fold, stage 1: partial Wc over k-slices.  grid (32, 8), block 256 ------
__global__ void fold_part_kernel(const float* __restrict__ Wf,
                                 const float* __restrict__ Wo1,
                                 float* __restrict__ part) {
    __shared__ float sWf[8][32];
    const int t = threadIdx.x, o0 = blockIdx.x * 8, kz = blockIdx.y * 32;
    {
        int r = t >> 5, hh = t & 31;
        sWf[r][hh] = Wf[(o0 + r) * 256 + kz + hh];
    }
    __syncthreads();
    float acc[8] = {0,0,0,0,0,0,0,0};
    #pragma unroll
    for (int hh = 0; hh < 32; ++hh) {
        float x = Wo1[(kz + hh) * 256 + t];
        #pragma unroll
        for (int r = 0; r < 8; ++r) acc[r] = fmaf(sWf[r][hh], x, acc[r]);
    }
    #pragma unroll
    for (int r = 0; r < 8; ++r)
        part[((size_t)blockIdx.y << 16) + (o0 + r) * 256 + t] = acc[r];
}

// ---- fold, stage 2: reduce partials, fp16 hi, compute bc --------------------
__global__ void fold_reduce_kernel(const float* __restrict__ part,
                                   const float* __restrict__ Wf,
                                   const float* __restrict__ bo1,
                                   const float* __restrict__ bfb,
                                   __half* __restrict__ Wch,
                                   float* __restrict__ bc) {
    const int o = blockIdx.x, t = threadIdx.x;
    float v = 0.f;
    #pragma unroll
    for (int kz = 0; kz < 8; ++kz) v += part[((size_t)kz << 16) + o * 256 + t];
    Wch[o * 256 + t] = __float2half_rn(v);

    __shared__ float red[256];
    red[t] = Wf[o * 256 + t] * bo1[t];
    __syncthreads();
    #pragma unroll
    for (int s = 128; s > 0; s >>= 1) {
        if (t < s) red[t] += red[t + s];
        __syncthreads();
    }
    if (t == 0) bc[o] = red[0] + bfb[o];
}

// ---------------- wide-tile mma.sync GEMM ------------------------------------
// C[M, 256] = act(A @ W^T + bias).  CTA tile 128(M) x 256(N) x 32(K).
// 8 warps 2Mx4N, warp tile 64x64 -> A smem-read 4x, B 2x: LDS 1024cyc vs
// tensor 1536cyc per stage (PASSES=3) -> tensor-bound.
// PASSES=3: STAGES=2 (61440B/stage); PASSES=1: STAGES=4 (30720B/stage).
// Row stride 80B (64B payload + 16B pad) -> ldmatrix conflict-free.

template<int PASSES, bool GATHER, bool RELU>
__global__ void __launch_bounds__(256)
gemm3(const __half* __restrict__ Ah, const __half* __restrict__ Al,
      const __half* __restrict__ Wh, const __half* __restrict__ Wl,
      const float* __restrict__ bias, float* __restrict__ C,
      int Mtiles) {
    constexpr int NA     = (PASSES == 3) ? 2 : 1;           // A (and B) arrays
    constexpr int STAGES = (PASSES == 3) ? 2 : 4;
    constexpr uint32_t ABYT = 10240;                        // 128 rows * 80B
    constexpr uint32_t BBYT = 20480;                        // 256 rows * 80B
    constexpr uint32_t STG  = NA * (ABYT + BBYT);
    constexpr int ACH = NA * 512;                           // 16B chunks of A
    constexpr int NCH = NA * 1536;                          // total chunks

    extern __shared__ char smem[];
    const uint32_t sb = smem_u32(smem);
    float* sbias = (float*)(smem + STAGES * STG);
    const int t = threadIdx.x, lane = t & 31, wid = t >> 5;

    const int tb  = blockIdx.x;
    const int NTB = gridDim.x;

    sbias[t] = bias[t];
    if (t < 128) { }   // (256 threads cover 256 bias entries exactly)

    int tiles = 0;
    for (int mt = tb; mt < Mtiles; mt += NTB) ++tiles;
    const int QS = tiles * 8;

    auto cp_stage = [&](int q) {
        const int lt = q >> 3, kt = q & 7;
        const int mt = tb + lt * NTB;
        const uint32_t db = sb + (uint32_t)(q & (STAGES - 1)) * STG;
        #pragma unroll
        for (int u = 0; u < NCH / 256; ++u) {
            const int s = t + (u << 8);
            uint32_t dst;
            const __half* src;
            if (s < ACH) {                       // A: NA arrays x 128 rows x 4 segs
                const int id  = s >> 9;
                const int rem = s & 511;
                const int row = rem >> 2, seg = rem & 3;
                dst = db + (uint32_t)(id * ABYT + row * 80 + seg * 16);
                int g = mt * 128 + row;
                if (GATHER) g = (g >> 2) * 12 + 3 * (g & 3);
                src = (id ? Al : Ah) + (size_t)g * 256 + kt * 32 + seg * 8;
            } else {                             // B: NA arrays x 256 rows x 4 segs
                const int sB  = s - ACH;
                const int id  = sB >> 10;
                const int rem = sB & 1023;
                const int row = rem >> 2, seg = rem & 3;
                dst = db + (uint32_t)(NA * ABYT + id * BBYT + row * 80 + seg * 16);
                src = (id ? Wl : Wh) + row * 256 + kt * 32 + seg * 8;
            }
            cp16(dst, src);
        }
        asm volatile("cp.async.commit_group;\n" ::: "memory");
    };

    const int wm = (wid & 1) * 64;        // 2 warps in M
    const int wn = (wid >> 1) * 64;       // 4 warps in N, 64 cols each
    const uint32_t aoff = (uint32_t)((wm + (lane & 15)) * 80 + ((lane >> 4) << 4));
    const uint32_t boff = (uint32_t)((lane & 7) * 80 + (((lane >> 3) & 1) << 4));

    float c[4][8][4];
    #pragma unroll
    for (int i = 0; i < 4; ++i)
        #pragma unroll
        for (int j = 0; j < 8; ++j)
            #pragma unroll
            for (int e = 0; e < 4; ++e) c[i][j][e] = 0.f;

    const int npre = QS < (STAGES - 1) ? QS : (STAGES - 1);
    for (int q = 0; q < npre; ++q) cp_stage(q);

    for (int q = 0; q < QS; ++q) {
        const int kt = q & 7;
        if constexpr (STAGES == 2)
            asm volatile("cp.async.wait_group 0;\n" ::: "memory");
        else
            asm volatile("cp.async.wait_group 2;\n" ::: "memory");
        __syncthreads();
        if (q + STAGES - 1 < QS) cp_stage(q + STAGES - 1);

        {
            const uint32_t ab = sb + (uint32_t)(q & (STAGES - 1)) * STG;
            const uint32_t bhbase = ab + NA * ABYT;
            #pragma unroll
            for (int ks = 0; ks < 32; ks += 16) {
                uint32_t rbh[8][2], rah[4][4];
                #pragma unroll
                for (int j = 0; j < 8; ++j) {
                    const uint32_t o = boff + (uint32_t)((wn + 8 * j) * 80 + ks * 2);
                    ldmatrix_x2(rbh[j][0], rbh[j][1], bhbase + o);
                }
                #pragma unroll
                for (int i = 0; i < 4; ++i) {
                    const uint32_t o = aoff + (uint32_t)(i * 16 * 80 + ks * 2);
                    ldmatrix_x4(rah[i][0], rah[i][1], rah[i][2], rah[i][3], ab + o);
                }
                // pass 1: hi*hi (32 independent mma)
                #pragma unroll
                for (int i = 0; i < 4; ++i)
                    #pragma unroll
                    for (int j = 0; j < 8; ++j)
                        mma_f16(c[i][j], rah[i][0], rah[i][1], rah[i][2], rah[i][3],
                                rbh[j][0], rbh[j][1]);
                if constexpr (PASSES == 3) {
                    {   // pass 2: hi*lo  (rbl scope minimized)
                        uint32_t rbl[8][2];
                        const uint32_t blbase = bhbase + BBYT;
                        #pragma unroll
                        for (int j = 0; j < 8; ++j) {
                            const uint32_t o = boff + (uint32_t)((wn + 8 * j) * 80 + ks * 2);
                            ldmatrix_x2(rbl[j][0], rbl[j][1], blbase + o);
                        }
                        #pragma unroll
                        for (int i = 0; i < 4; ++i)
                            #pragma unroll
                            for (int j = 0; j < 8; ++j)
                                mma_f16(c[i][j], rah[i][0], rah[i][1], rah[i][2], rah[i][3],
                                        rbl[j][0], rbl[j][1]);
                    }
                    {   // pass 3: lo*hi
                        uint32_t ral[4][4];
                        const uint32_t albase = ab + ABYT;
                        #pragma unroll
                        for (int i = 0; i < 4; ++i) {
                            const uint32_t o = aoff + (uint32_t)(i * 16 * 80 + ks * 2);
                            ldmatrix_x4(ral[i][0], ral[i][1], ral[i][2], ral[i][3], albase + o);
                        }
                        #pragma unroll
                        for (int i = 0; i < 4; ++i)
                            #pragma unroll
                            for (int j = 0; j < 8; ++j)
                                mma_f16(c[i][j], ral[i][0], ral[i][1], ral[i][2], ral[i][3],
                                        rbh[j][0], rbh[j][1]);
                    }
                }
            }
        }

        if (kt == 7) {
            const int mt = tb + (q >> 3) * NTB;
            const int gr = lane >> 2, gc = (lane & 3) * 2;
            const int mbase = mt * 128 + wm;
            #pragma unroll
            for (int i = 0; i < 4; ++i) {
                #pragma unroll
                for (int j = 0; j < 8; ++j) {
                    const int col = wn + 8 * j + gc;
                    const float b0v = sbias[col], b1v = sbias[col + 1];
                    float v0 = c[i][j][0] + b0v, v1 = c[i][j][1] + b1v;
                    float v2 = c[i][j][2] + b0v, v3 = c[i][j][3] + b1v;
                    if (RELU) {
                        v0 = fmaxf(v0, 0.f); v1 = fmaxf(v1, 0.f);
                        v2 = fmaxf(v2, 0.f); v3 = fmaxf(v3, 0.f);
                    }
                    const int r0 = mbase + 16 * i + gr;
                    *(float2*)&C[(size_t)r0 * 256 + col]       = make_float2(v0, v1);
                    *(float2*)&C[(size_t)(r0 + 8) * 256 + col] = make_float2(v2, v3);
                    c[i][j][0] = 0.f; c[i][j][1] = 0.f;
                    c[i][j][2] = 0.f; c[i][j][3] = 0.f;
                }
            }
        }
    }
}

// ---------------- attention ---------------------------------------------------
// block = 128 thr = one batch; warp w -> sel row (node 3w). f1 written fp16.
__global__ void __launch_bounds__(128)
attn_kernel(const float* __restrict__ q1, const float* __restrict__ k1,
            const float* __restrict__ wh1, const float* __restrict__ label,
            const float* __restrict__ adj, __half* __restrict__ f1h) {
    __shared__ float sk [NNODE * 256];
    __shared__ float swh[NNODE * 256];
    __shared__ float sq [4 * 256];
    __shared__ float sadj[4 * NNODE];
    __shared__ float slab[NNODE];

    const int b = blockIdx.x, t = threadIdx.x;

    const float4* k4 = (const float4*)(k1  + (size_t)b * NNODE * 256);
    const float4* w4 = (const float4*)(wh1 + (size_t)b * NNODE * 256);
    const float4* q4 = (const float4*)(q1  + (size_t)b * 4 * 256);
    float4* dk = (float4*)sk;
    float4* dw = (float4*)swh;
    float4* dq = (float4*)sq;
    #pragma unroll
    for (int u = 0; u < 6; ++u) { dk[t + 128 * u] = k4[t + 128 * u];
                                  dw[t + 128 * u] = w4[t + 128 * u]; }
    #pragma unroll
    for (int u = 0; u < 2; ++u)   dq[t + 128 * u] = q4[t + 128 * u];
    if (t < NNODE) slab[t] = label[b * NNODE + t];
    if (t < 4 * NNODE) {
        int i = t / NNODE, m = t % NNODE;
        sadj[t] = adj[(3 * i) * NNODE + m];
    }
    __syncthreads();

    const int w = t >> 5, l = t & 31;
    float qv[8];
    {
        const float4* qp = (const float4*)(sq + w * 256 + l * 8);
        float4 a = qp[0], bq_ = qp[1];
        qv[0]=a.x; qv[1]=a.y; qv[2]=a.z; qv[3]=a.w;
        qv[4]=bq_.x; qv[5]=bq_.y; qv[6]=bq_.z; qv[7]=bq_.w;
    }
    float s[NNODE];
    #pragma unroll
    for (int m = 0; m < NNODE; ++m) {
        const float4* kp = (const float4*)(sk + m * 256 + l * 8);
        float4 a = kp[0], bb = kp[1];
        s[m] = qv[0]*a.x + qv[1]*a.y + qv[2]*a.z + qv[3]*a.w
             + qv[4]*bb.x + qv[5]*bb.y + qv[6]*bb.z + qv[7]*bb.w;
    }
    #pragma unroll
    for (int m = 0; m < NNODE; ++m)
        #pragma unroll
        for (int off = 16; off > 0; off >>= 1)
            s[m] += __shfl_xor_sync(0xffffffffu, s[m], off);

    float mx = -3.0e38f;
    #pragma unroll
    for (int m = 0; m < NNODE; ++m) {
        float sm = (sadj[w * NNODE + m] > 0.5f) ? s[m] : -9.0e15f;
        s[m] = sm;
        mx = fmaxf(mx, sm);
    }
    float sum = 0.f;
    #pragma unroll
    for (int m = 0; m < NNODE; ++m) { float p = expf(s[m] - mx); s[m] = p; sum += p; }
    const float inv = 1.f / sum;
    #pragma unroll
    for (int m = 0; m < NNODE; ++m) s[m] = s[m] * inv * slab[m];

    float o[8] = {0,0,0,0,0,0,0,0};
    #pragma unroll
    for (int m = 0; m < NNODE; ++m) {
        const float4* wp = (const float4*)(swh + m * 256 + l * 8);
        float4 a = wp[0], bb = wp[1];
        float am = s[m];
        o[0] = fmaf(am, a.x, o[0]); o[1] = fmaf(am, a.y, o[1]);
        o[2] = fmaf(am, a.z, o[2]); o[3] = fmaf(am, a.w, o[3]);
        o[4] = fmaf(am, bb.x, o[4]); o[5] = fmaf(am, bb.y, o[5]);
        o[6] = fmaf(am, bb.z, o[6]); o[7] = fmaf(am, bb.w, o[7]);
    }
    uint32_t pk[4];
    #pragma unroll
    for (int g = 0; g < 4; ++g) {
        __half2 h2 = __floats2half2_rn(o[2*g], o[2*g+1]);
        pk[g] = *(uint32_t*)&h2;
    }
    const size_t idx = (size_t)(b * 4 + w) * 256 + l * 8;
    *(uint4*)(f1h + idx) = make_uint4(pk[0], pk[1], pk[2], pk[3]);
}

// ---------------- host launch -------------------------------------------------
extern "C" void kernel_launch(void* const* d_in, const int* in_sizes, int n_in,
                              void* d_out, int out_size) {
    const float* h     = (const float*)d_in[0];
    const float* adj   = (const float*)d_in[1];
    const float* label = (const float*)d_in[2];
    const float* Wv    = (const float*)d_in[3];
    const float* bv    = (const float*)d_in[4];
    const float* Wk    = (const float*)d_in[5];
    const float* bk    = (const float*)d_in[6];
    const float* Wq    = (const float*)d_in[7];
    const float* bq    = (const float*)d_in[8];
    const float* Wo1   = (const float*)d_in[9];
    const float* bo1   = (const float*)d_in[10];
    const float* Wf    = (const float*)d_in[11];
    const float* bf    = (const float*)d_in[12];
    float* out = (float*)d_out;

    float *p_Wh1, *p_k1, *p_q1, *p_bc, *p_part;
    __half *p_hh, *p_hl, *p_f1h;
    __half *p_Wvh, *p_Wvl, *p_Wkh, *p_Wkl, *p_Wqh, *p_Wql, *p_Wch;
    cudaGetSymbolAddress((void**)&p_Wh1, g_Wh1);
    cudaGetSymbolAddress((void**)&p_k1,  g_k1);
    cudaGetSymbolAddress((void**)&p_q1,  g_q1);
    cudaGetSymbolAddress((void**)&p_bc,  g_bc);
    cudaGetSymbolAddress((void**)&p_part, g_Wc_part);
    cudaGetSymbolAddress((void**)&p_hh,  g_hh);
    cudaGetSymbolAddress((void**)&p_hl,  g_hl);
    cudaGetSymbolAddress((void**)&p_f1h, g_f1h);
    cudaGetSymbolAddress((void**)&p_Wvh, g_Wv_h);
    cudaGetSymbolAddress((void**)&p_Wvl, g_Wv_l);
    cudaGetSymbolAddress((void**)&p_Wkh, g_Wk_h);
    cudaGetSymbolAddress((void**)&p_Wkl, g_Wk_l);
    cudaGetSymbolAddress((void**)&p_Wqh, g_Wq_h);
    cudaGetSymbolAddress((void**)&p_Wql, g_Wq_l);
    cudaGetSymbolAddress((void**)&p_Wch, g_Wc_h);

    const int SMEM3 = 2 * 61440 + 1024;   // 2-stage fp16x3, 128x256 tile
    const int SMEM1 = 4 * 30720 + 1024;   // 4-stage fp16x1, 128x256 tile
    cudaFuncSetAttribute(gemm3<3, false, true>,
                         cudaFuncAttributeMaxDynamicSharedMemorySize, SMEM3);
    cudaFuncSetAttribute(gemm3<3, true, true>,
                         cudaFuncAttributeMaxDynamicSharedMemorySize, SMEM3);
    cudaFuncSetAttribute(gemm3<1, false, true>,
                         cudaFuncAttributeMaxDynamicSharedMemorySize, SMEM1);
    cudaFuncSetAttribute(gemm3<1, false, false>,
                         cudaFuncAttributeMaxDynamicSharedMemorySize, SMEM1);

    // Launch order keeps the big K-GEMM at index 4 (the launch ncu captures).
    convert_h_kernel<<<12288, 256>>>(h, p_hh, p_hl);             // 1
    convert_w_kernel<<<256, 256>>>(Wv, p_Wvh, p_Wvl);            // 2
    convert_w_kernel<<<256, 256>>>(Wk, p_Wkh, p_Wkl);            // 3
    // K GEMM (fp16x3): k1 = relu(h@Wk^T + bk)                   // 4
    gemm3<3, false, true><<<148, 256, SMEM3>>>(
        p_hh, p_hl, p_Wkh, p_Wkl, bk, p_k1, M_VK / 128);
    // V GEMM (fp16x1): Wh1 = relu(h@Wv^T + bv)                  // 5
    gemm3<1, false, true><<<148, 256, SMEM1>>>(
        p_hh, nullptr, p_Wvh, nullptr, bv, p_Wh1, M_VK / 128);
    convert_w_kernel<<<256, 256>>>(Wq, p_Wqh, p_Wql);            // 6
    // Q GEMM (fp16x3, gathered): q1 = relu(h_sel@Wq^T + bq)     // 7
    gemm3<3, true, true><<<148, 256, SMEM3>>>(
        p_hh, p_hl, p_Wqh, p_Wql, bq, p_q1, M_SEL / 128);
    fold_part_kernel<<<dim3(32, 8), 256>>>(Wf, Wo1, p_part);     // 8
    fold_reduce_kernel<<<256, 256>>>(p_part, Wf, bo1, bf, p_Wch, p_bc);  // 9
    attn_kernel<<<BATCH, 128>>>(p_q1, p_k1, p_Wh1, label, adj, p_f1h);   // 10
    // out GEMM (fp16x1) straight into d_out                     // 11
    gemm3<1, false, false><<<148, 256, SMEM1>>>(
        p_f1h, nullptr, p_Wch, nullptr, p_bc, out, M_SEL / 128);
}

// round 11
// speedup vs baseline: 1.1500x; 1.1500x over previous
#include <cuda_runtime.h>
#include <cuda_fp16.h>
#include <cstdint>
#include <cstddef>

// ============================================================================
// GAT fusion, B=8192, N=12, D=256, SEL={0,3,6,9}.  sm_100 legacy-mma edition.
// Measured: mma.sync f32-accum runs ~2x slower than ncu peak (ceiling ~52%)
// regardless of tiling -> GEMM config frozen at R8's best (128x128, 2 CTA/SM).
// This round: Wh1 stored fp16 (V epilogue + attention), fused weight converts.
// K,Q fp16x3 (softmax-accurate); V,out fp16x1.
// ============================================================================

#define BATCH   8192
#define NNODE   12
#define DIM     256
#define M_VK    (BATCH * NNODE)     // 98304
#define M_SEL   (BATCH * 4)         // 32768

// ---------------- scratch (device globals; no allocation) -------------------
__device__ __half g_hh[M_VK * DIM], g_hl[M_VK * DIM];    // h split (fp16)
__device__ __half g_Wh1[M_VK * DIM];                      // V output, fp16
__device__ float g_k1 [M_VK * DIM];
__device__ float g_q1 [M_SEL * DIM];
__device__ __half g_f1h[M_SEL * DIM];
__device__ float g_bc [DIM];
__device__ float g_Wc_part[8 * DIM * DIM];
__device__ __half g_Wv_h[DIM*DIM], g_Wv_l[DIM*DIM];
__device__ __half g_Wk_h[DIM*DIM], g_Wk_l[DIM*DIM];
__device__ __half g_Wq_h[DIM*DIM], g_Wq_l[DIM*DIM];
__device__ __half g_Wc_h[DIM*DIM];

// ---------------- helpers ----------------------------------------------------
__device__ __forceinline__ uint32_t smem_u32(const void* p) {
    return (uint32_t)__cvta_generic_to_shared(p);
}
__device__ __forceinline__ void ldmatrix_x4(uint32_t& r0, uint32_t& r1,
                                            uint32_t& r2, uint32_t& r3, uint32_t addr) {
    asm volatile("ldmatrix.sync.aligned.m8n8.x4.shared.b16 {%0,%1,%2,%3}, [%4];\n"
                 : "=r"(r0), "=r"(r1), "=r"(r2), "=r"(r3) : "r"(addr));
}
__device__ __forceinline__ void ldmatrix_x2(uint32_t& r0, uint32_t& r1, uint32_t addr) {
    asm volatile("ldmatrix.sync.aligned.m8n8.x2.shared.b16 {%0,%1}, [%2];\n"
                 : "=r"(r0), "=r"(r1) : "r"(addr));
}
__device__ __forceinline__ void mma_f16(float c[4],
                                        uint32_t a0, uint32_t a1, uint32_t a2, uint32_t a3,
                                        uint32_t b0, uint32_t b1) {
    asm volatile("mma.sync.aligned.m16n8k16.row.col.f32.f16.f16.f32 "
                 "{%0,%1,%2,%3}, {%4,%5,%6,%7}, {%8,%9}, {%0,%1,%2,%3};\n"
                 : "+f"(c[0]), "+f"(c[1]), "+f"(c[2]), "+f"(c[3])
                 : "r"(a0), "r"(a1), "r"(a2), "r"(a3), "r"(b0), "r"(b1));
}
__device__ __forceinline__ void cp16(uint32_t dst, const void* src) {
    asm volatile("cp.async.cg.shared.global [%0], [%1], 16;\n" :: "r"(dst), "l"(src));
}

// ---------------- prologue kernels -------------------------------------------
// all three attention weights in one launch: grid (256, 3)
__global__ void convert_w3_kernel(const float* __restrict__ s0, __half* __restrict__ h0, __half* __restrict__ l0,
                                  const float* __restrict__ s1, __half* __restrict__ h1, __half* __restrict__ l1,
                                  const float* __restrict__ s2, __half* __restrict__ h2, __half* __restrict__ l2) {
    const float* s; __half *hh, *ll;
    if (blockIdx.y == 0)      { s = s0; hh = h0; ll = l0; }
    else if (blockIdx.y == 1) { s = s1; hh = h1; ll = l1; }
    else                      { s = s2; hh = h2; ll = l2; }
    int i = blockIdx.x * 256 + threadIdx.x;
    float x = s[i];
    __half v = __float2half_rn(x);
    hh[i] = v;
    ll[i] = __float2half_rn(x - __half2float(v));
}

__global__ void convert_h_kernel(const float* __restrict__ src,
                                 __half* __restrict__ hi,
                                 __half* __restrict__ lo) {
    size_t i = ((size_t)blockIdx.x * 256 + threadIdx.x) * 8;
    float4 a = *(const float4*)(src + i);
    float4 b = *(const float4*)(src + i + 4);
    float x[8] = {a.x, a.y, a.z, a.w, b.x, b.y, b.z, b.w};
    uint32_t hw[4], lw[4];
    #pragma unroll
    for (int g = 0; g < 4; ++g) {
        __half h0 = __float2half_rn(x[2*g]);
        __half h1 = __float2half_rn(x[2*g+1]);
        __half l0 = __float2half_rn(x[2*g]   - __half2float(h0));
        __half l1 = __float2half_rn(x[2*g+1] - __half2float(h1));
        hw[g] = (uint32_t)__half_as_ushort(h0) | ((uint32_t)__half_as_ushort(h1) << 16);
        lw[g] = (uint32_t)__half_as_ushort(l0) | ((uint32_t)__half_as_ushort(l1) << 16);
    }
    *(uint4*)(hi + i) = make_uint4(hw[0], hw[1], hw[2], hw[3]);
    *(uint4*)(lo + i) = make_uint4(lw[0], lw[1], lw[2], lw[3]);
}

// ---- fold, stage 1: partial Wc over k-slices.  grid (32, 8), block 256 ------
__global__ void fold_part_kernel(const float* __restrict__ Wf,
                                 const float* __restrict__ Wo1,
                                 float* __restrict__ part) {
    __shared__ float sWf[8][32];
    const int t = threadIdx.x, o0 = blockIdx.x * 8, kz = blockIdx.y * 32;
    {
        int r = t >> 5, hh = t & 31;
        sWf[r][hh] = Wf[(o0 + r) * 256 + kz + hh];
    }
    __syncthreads();
    float acc[8] = {0,0,0,0,0,0,0,0};
    #pragma unroll
    for (int hh = 0; hh < 32; ++hh) {
        float x = Wo1[(kz + hh) * 256 + t];
        #pragma unroll
        for (int r = 0; r < 8; ++r) acc[r] = fmaf(sWf[r][hh], x, acc[r]);
    }
    #pragma unroll
    for (int r = 0; r < 8; ++r)
        part[((size_t)blockIdx.y << 16) + (o0 + r) * 256 + t] = acc[r];
}

// ---- fold, stage 2: reduce partials, fp16 hi, compute bc --------------------
__global__ void fold_reduce_kernel(const float* __restrict__ part,
                                   const float* __restrict__ Wf,
                                   const float* __restrict__ bo1,
                                   const float* __restrict__ bfb,
                                   __half* __restrict__ Wch,
                                   float* __restrict__ bc) {
    const int o = blockIdx.x, t = threadIdx.x;
    float v = 0.f;
    #pragma unroll
    for (int kz = 0; kz < 8; ++kz) v += part[((size_t)kz << 16) + o * 256 + t];
    Wch[o * 256 + t] = __float2half_rn(v);

    __shared__ float red[256];
    red[t] = Wf[o * 256 + t] * bo1[t];
    __syncthreads();
    #pragma unroll
    for (int s = 128; s > 0; s >>= 1) {
        if (t < s) red[t] += red[t + s];
        __syncthreads();
    }
    if (t == 0) bc[o] = red[0] + bfb[o];
}

// ---------------- pipelined mma.sync GEMM (R8 config, frozen) ----------------
// C[M, 128 cols @ ncol0] = act(A @ W^T + bias). fp16 operands, fp32 accum.
// PASSES=3: STAGES=2, arrays {Ah,Al,Bh,Bl}; PASSES=1: STAGES=4, arrays {Ah,Bh}.
// 82KB dynamic smem -> 2 CTAs/SM.  OUTH: epilogue stores __half instead of f32.

template<int PASSES, bool GATHER, bool RELU, bool OUTH>
__global__ void __launch_bounds__(256, 2)
gemm2(const __half* __restrict__ Ah, const __half* __restrict__ Al,
      const __half* __restrict__ Wh, const __half* __restrict__ Wl,
      const float* __restrict__ bias, void* __restrict__ Cv,
      int Mtiles) {
    constexpr int ARR    = (PASSES == 3) ? 4 : 2;
    constexpr int NA     = (PASSES == 3) ? 2 : 1;
    constexpr int STAGES = (PASSES == 3) ? 2 : 4;
    constexpr uint32_t STG = ARR * 10240;

    extern __shared__ char smem[];
    const uint32_t sb = smem_u32(smem);
    float* sbias = (float*)(smem + STAGES * STG);
    const int t = threadIdx.x, lane = t & 31, wid = t >> 5;

    const int y   = blockIdx.x & 1;
    const int tb  = blockIdx.x >> 1;
    const int NTB = gridDim.x >> 1;
    const int ncol0 = y * 128;

    if (t < 128) sbias[t] = bias[ncol0 + t];

    int tiles = 0;
    for (int mt = tb; mt < Mtiles; mt += NTB) ++tiles;
    const int QS = tiles * 8;

    auto cp_stage = [&](int q) {
        const int lt = q >> 3, kt = q & 7;
        const int mt = tb + lt * NTB;
        const uint32_t db = sb + (uint32_t)(q & (STAGES - 1)) * STG;
        #pragma unroll
        for (int u = 0; u < ARR * 2; ++u) {
            const int s = t + (u << 8);
            const int id  = s >> 9;
            const int row = (s >> 2) & 127;
            const int seg = s & 3;
            const uint32_t dst = db + (uint32_t)(id * 10240 + row * 80 + seg * 16);
            const __half* src;
            if (id < NA) {
                int g = mt * 128 + row;
                if (GATHER) g = (g >> 2) * 12 + 3 * (g & 3);
                src = (id ? Al : Ah) + (size_t)g * 256 + kt * 32 + seg * 8;
            } else {
                src = ((id - NA) ? Wl : Wh) + (ncol0 + row) * 256 + kt * 32 + seg * 8;
            }
            cp16(dst, src);
        }
        asm volatile("cp.async.commit_group;\n" ::: "memory");
    };

    const int wm = (wid & 1) * 64;
    const int wn = (wid >> 1) * 32;
    const uint32_t aoff = (uint32_t)((wm + (lane & 15)) * 80 + ((lane >> 4) << 4));
    const uint32_t boff = (uint32_t)((lane & 7) * 80 + (((lane >> 3) & 1) << 4));

    float c[4][4][4];
    #pragma unroll
    for (int i = 0; i < 4; ++i)
        #pragma unroll
        for (int j = 0; j < 4; ++j)
            #pragma unroll
            for (int e = 0; e < 4; ++e) c[i][j][e] = 0.f;

    const int npre = QS < (STAGES - 1) ? QS : (STAGES - 1);
    for (int q = 0; q < npre; ++q) cp_stage(q);

    for (int q = 0; q < QS; ++q) {
        const int kt = q & 7;
        if constexpr (STAGES == 2)
            asm volatile("cp.async.wait_group 0;\n" ::: "memory");
        else
            asm volatile("cp.async.wait_group 2;\n" ::: "memory");
        __syncthreads();
        if (q + STAGES - 1 < QS) cp_stage(q + STAGES - 1);

        {
            const uint32_t ab     = sb + (uint32_t)(q & (STAGES - 1)) * STG;
            const uint32_t albase = ab + 10240;
            const uint32_t bhbase = ab + NA * 10240;
            const uint32_t blbase = bhbase + 10240;
            #pragma unroll
            for (int ks = 0; ks < 32; ks += 16) {
                uint32_t rbh[4][2], rah[4][4];
                #pragma unroll
                for (int j = 0; j < 4; ++j) {
                    const uint32_t o = boff + (uint32_t)((wn + 8 * j) * 80 + ks * 2);
                    ldmatrix_x2(rbh[j][0], rbh[j][1], bhbase + o);
                }
                #pragma unroll
                for (int i = 0; i < 4; ++i) {
                    const uint32_t o = aoff + (uint32_t)(i * 16 * 80 + ks * 2);
                    ldmatrix_x4(rah[i][0], rah[i][1], rah[i][2], rah[i][3], ab + o);
                }
                #pragma unroll
                for (int i = 0; i < 4; ++i)
                    #pragma unroll
                    for (int j = 0; j < 4; ++j)
                        mma_f16(c[i][j], rah[i][0], rah[i][1], rah[i][2], rah[i][3],
                                rbh[j][0], rbh[j][1]);
                if constexpr (PASSES == 3) {
                    uint32_t rbl[4][2], ral[4][4];
                    #pragma unroll
                    for (int j = 0; j < 4; ++j) {
                        const uint32_t o = boff + (uint32_t)((wn + 8 * j) * 80 + ks * 2);
                        ldmatrix_x2(rbl[j][0], rbl[j][1], blbase + o);
                    }
                    #pragma unroll
                    for (int i = 0; i < 4; ++i) {
                        const uint32_t o = aoff + (uint32_t)(i * 16 * 80 + ks * 2);
                        ldmatrix_x4(ral[i][0], ral[i][1], ral[i][2], ral[i][3], albase + o);
                    }
                    #pragma unroll
                    for (int i = 0; i < 4; ++i)
                        #pragma unroll
                        for (int j = 0; j < 4; ++j)
                            mma_f16(c[i][j], rah[i][0], rah[i][1], rah[i][2], rah[i][3],
                                    rbl[j][0], rbl[j][1]);
                    #pragma unroll
                    for (int i = 0; i < 4; ++i)
                        #pragma unroll
                        for (int j = 0; j < 4; ++j)
                            mma_f16(c[i][j], ral[i][0], ral[i][1], ral[i][2], ral[i][3],
                                    rbh[j][0], rbh[j][1]);
                }
            }
        }

        if (kt == 7) {
            const int mt = tb + (q >> 3) * NTB;
            const int gr = lane >> 2, gc = (lane & 3) * 2;
            const int mbase = mt * 128 + wm;
            #pragma unroll
            for (int i = 0; i < 4; ++i) {
                #pragma unroll
                for (int j = 0; j < 4; ++j) {
                    const int col = wn + 8 * j + gc;
                    const float b0v = sbias[col], b1v = sbias[col + 1];
                    float v0 = c[i][j][0] + b0v, v1 = c[i][j][1] + b1v;
                    float v2 = c[i][j][2] + b0v, v3 = c[i][j][3] + b1v;
                    if (RELU) {
                        v0 = fmaxf(v0, 0.f); v1 = fmaxf(v1, 0.f);
                        v2 = fmaxf(v2, 0.f); v3 = fmaxf(v3, 0.f);
                    }
                    const int r0 = mbase + 16 * i + gr;
                    if constexpr (OUTH) {
                        __half* C = (__half*)Cv;
                        *(__half2*)&C[(size_t)r0 * 256 + ncol0 + col] =
                            __floats2half2_rn(v0, v1);
                        *(__half2*)&C[(size_t)(r0 + 8) * 256 + ncol0 + col] =
                            __floats2half2_rn(v2, v3);
                    } else {
                        float* C = (float*)Cv;
                        *(float2*)&C[(size_t)r0 * 256 + ncol0 + col]       = make_float2(v0, v1);
                        *(float2*)&C[(size_t)(r0 + 8) * 256 + ncol0 + col] = make_float2(v2, v3);
                    }
                    c[i][j][0] = 0.f; c[i][j][1] = 0.f;
                    c[i][j][2] = 0.f; c[i][j][3] = 0.f;
                }
            }
        }
    }
}

// ---------------- attention ---------------------------------------------------
// block = 128 thr = one batch; warp w -> sel row (node 3w).
// k1,q1 fp32; Wh1 fp16; f1 written fp16.
__global__ void __launch_bounds__(128)
attn_kernel(const float* __restrict__ q1, const float* __restrict__ k1,
            const __half* __restrict__ wh1, const float* __restrict__ label,
            const float* __restrict__ adj, __half* __restrict__ f1h) {
    __shared__ float  sk [NNODE * 256];
    __shared__ __half swh[NNODE * 256];
    __shared__ float  sq [4 * 256];
    __shared__ float  sadj[4 * NNODE];
    __shared__ float  slab[NNODE];

    const int b = blockIdx.x, t = threadIdx.x;

    const float4* k4 = (const float4*)(k1  + (size_t)b * NNODE * 256);
    const uint4*  w4 = (const uint4*)(wh1 + (size_t)b * NNODE * 256);
    const float4* q4 = (const float4*)(q1  + (size_t)b * 4 * 256);
    float4* dk = (float4*)sk;
    uint4*  dw = (uint4*)swh;                      // 3072 halves = 384 uint4
    float4* dq = (float4*)sq;
    #pragma unroll
    for (int u = 0; u < 6; ++u) dk[t + 128 * u] = k4[t + 128 * u];
    #pragma unroll
    for (int u = 0; u < 3; ++u) dw[t + 128 * u] = w4[t + 128 * u];
    #pragma unroll
    for (int u = 0; u < 2; ++u) dq[t + 128 * u] = q4[t + 128 * u];
    if (t < NNODE) slab[t] = label[b * NNODE + t];
    if (t < 4 * NNODE) {
        int i = t / NNODE, m = t % NNODE;
        sadj[t] = adj[(3 * i) * NNODE + m];
    }
    __syncthreads();

    const int w = t >> 5, l = t & 31;
    float qv[8];
    {
        const float4* qp = (const float4*)(sq + w * 256 + l * 8);
        float4 a = qp[0], bq_ = qp[1];
        qv[0]=a.x; qv[1]=a.y; qv[2]=a.z; qv[3]=a.w;
        qv[4]=bq_.x; qv[5]=bq_.y; qv[6]=bq_.z; qv[7]=bq_.w;
    }
    float s[NNODE];
    #pragma unroll
    for (int m = 0; m < NNODE; ++m) {
        const float4* kp = (const float4*)(sk + m * 256 + l * 8);
        float4 a = kp[0], bb = kp[1];
        s[m] = qv[0]*a.x + qv[1]*a.y + qv[2]*a.z + qv[3]*a.w
             + qv[4]*bb.x + qv[5]*bb.y + qv[6]*bb.z + qv[7]*bb.w;
    }
    #pragma unroll
    for (int m = 0; m < NNODE; ++m)
        #pragma unroll
        for (int off = 16; off > 0; off >>= 1)
            s[m] += __shfl_xor_sync(0xffffffffu, s[m], off);

    float mx = -3.0e38f;
    #pragma unroll
    for (int m = 0; m < NNODE; ++m) {
        float sm = (sadj[w * NNODE + m] > 0.5f) ? s[m] : -9.0e15f;
        s[m] = sm;
        mx = fmaxf(mx, sm);
    }
    float sum = 0.f;
    #pragma unroll
    for (int m = 0; m < NNODE; ++m) { float p = expf(s[m] - mx); s[m] = p; sum += p; }
    const float inv = 1.f / sum;
    #pragma unroll
    for (int m = 0; m < NNODE; ++m) s[m] = s[m] * inv * slab[m];

    float o[8] = {0,0,0,0,0,0,0,0};
    #pragma unroll
    for (int m = 0; m < NNODE; ++m) {
        const __half2* wp = (const __half2*)(swh + m * 256 + l * 8);
        float2 a0 = __half22float2(wp[0]);
        float2 a1 = __half22float2(wp[1]);
        float2 a2 = __half22float2(wp[2]);
        float2 a3 = __half22float2(wp[3]);
        float am = s[m];
        o[0] = fmaf(am, a0.x, o[0]); o[1] = fmaf(am, a0.y, o[1]);
        o[2] = fmaf(am, a1.x, o[2]); o[3] = fmaf(am, a1.y, o[3]);
        o[4] = fmaf(am, a2.x, o[4]); o[5] = fmaf(am, a2.y, o[5]);
        o[6] = fmaf(am, a3.x, o[6]); o[7] = fmaf(am, a3.y, o[7]);
    }
    uint32_t pk[4];
    #pragma unroll
    for (int g = 0; g < 4; ++g) {
        __half2 h2 = __floats2half2_rn(o[2*g], o[2*g+1]);
        pk[g] = *(uint32_t*)&h2;
    }
    const size_t idx = (size_t)(b * 4 + w) * 256 + l * 8;
    *(uint4*)(f1h + idx) = make_uint4(pk[0], pk[1], pk[2], pk[3]);
}

// ---------------- host launch -------------------------------------------------
extern "C" void kernel_launch(void* const* d_in, const int* in_sizes, int n_in,
                              void* d_out, int out_size) {
    const float* h     = (const float*)d_in[0];
    const float* adj   = (const float*)d_in[1];
    const float* label = (const float*)d_in[2];
    const float* Wv    = (const float*)d_in[3];
    const float* bv    = (const float*)d_in[4];
    const float* Wk    = (const float*)d_in[5];
    const float* bk    = (const float*)d_in[6];
    const float* Wq    = (const float*)d_in[7];
    const float* bq    = (const float*)d_in[8];
    const float* Wo1   = (const float*)d_in[9];
    const float* bo1   = (const float*)d_in[10];
    const float* Wf    = (const float*)d_in[11];
    const float* bf    = (const float*)d_in[12];
    float* out = (float*)d_out;

    float *p_k1, *p_q1, *p_bc, *p_part;
    __half *p_hh, *p_hl, *p_f1h, *p_Wh1;
    __half *p_Wvh, *p_Wvl, *p_Wkh, *p_Wkl, *p_Wqh, *p_Wql, *p_Wch;
    cudaGetSymbolAddress((void**)&p_Wh1, g_Wh1);
    cudaGetSymbolAddress((void**)&p_k1,  g_k1);
    cudaGetSymbolAddress((void**)&p_q1,  g_q1);
    cudaGetSymbolAddress((void**)&p_bc,  g_bc);
    cudaGetSymbolAddress((void**)&p_part, g_Wc_part);
    cudaGetSymbolAddress((void**)&p_hh,  g_hh);
    cudaGetSymbolAddress((void**)&p_hl,  g_hl);
    cudaGetSymbolAddress((void**)&p_f1h, g_f1h);
    cudaGetSymbolAddress((void**)&p_Wvh, g_Wv_h);
    cudaGetSymbolAddress((void**)&p_Wvl, g_Wv_l);
    cudaGetSymbolAddress((void**)&p_Wkh, g_Wk_h);
    cudaGetSymbolAddress((void**)&p_Wkl, g_Wk_l);
    cudaGetSymbolAddress((void**)&p_Wqh, g_Wq_h);
    cudaGetSymbolAddress((void**)&p_Wql, g_Wq_l);
    cudaGetSymbolAddress((void**)&p_Wch, g_Wc_h);

    const int SMEM3 = 2 * 40960 + 1024;   // 2-stage fp16x3 -> 2 CTAs/SM
    const int SMEM1 = 4 * 20480 + 1024;   // 4-stage fp16x1 -> 2 CTAs/SM
    cudaFuncSetAttribute(gemm2<3, false, true, false>,
                         cudaFuncAttributeMaxDynamicSharedMemorySize, SMEM3);
    cudaFuncSetAttribute(gemm2<3, true, true, false>,
                         cudaFuncAttributeMaxDynamicSharedMemorySize, SMEM3);
    cudaFuncSetAttribute(gemm2<1, false, true, true>,
                         cudaFuncAttributeMaxDynamicSharedMemorySize, SMEM1);
    cudaFuncSetAttribute(gemm2<1, false, false, false>,
                         cudaFuncAttributeMaxDynamicSharedMemorySize, SMEM1);

    // Launch order keeps the big K-GEMM at index 4 (the launch ncu captures).
    convert_h_kernel<<<12288, 256>>>(h, p_hh, p_hl);                       // 1
    convert_w3_kernel<<<dim3(256, 3), 256>>>(Wv, p_Wvh, p_Wvl,
                                             Wk, p_Wkh, p_Wkl,
                                             Wq, p_Wqh, p_Wql);            // 2
    fold_part_kernel<<<dim3(32, 8), 256>>>(Wf, Wo1, p_part);               // 3
    // K GEMM (fp16x3): k1 = relu(h@Wk^T + bk), fp32 out                   // 4
    gemm2<3, false, true, false><<<296, 256, SMEM3>>>(
        p_hh, p_hl, p_Wkh, p_Wkl, bk, p_k1, M_VK / 128);
    // V GEMM (fp16x1): Wh1 = relu(h@Wv^T + bv), fp16 out                  // 5
    gemm2<1, false, true, true><<<296, 256, SMEM1>>>(
        p_hh, nullptr, p_Wvh, nullptr, bv, p_Wh1, M_VK / 128);
    // Q GEMM (fp16x3, gathered): q1 = relu(h_sel@Wq^T + bq), fp32 out     // 6
    gemm2<3, true, true, false><<<296, 256, SMEM3>>>(
        p_hh, p_hl, p_Wqh, p_Wql, bq, p_q1, M_SEL / 128);
    fold_reduce_kernel<<<256, 256>>>(p_part, Wf, bo1, bf, p_Wch, p_bc);    // 7
    attn_kernel<<<BATCH, 128>>>(p_q1, p_k1, p_Wh1, label, adj, p_f1h);     // 8
    // out GEMM (fp16x1) straight into d_out                               // 9
    gemm2<1, false, false, false><<<296, 256, SMEM1>>>(
        p_f1h, nullptr, p_Wch, nullptr, p_bc, out, M_SEL / 128);
}